// round 17
// baseline (speedup 1.0000x reference)
#include <cuda_runtime.h>
#include <cuda_fp16.h>
#include <cstdint>

// Problem shape (fixed by the dataset): N=50000 nodes, E=800000 edges, D=256.
#define DIM   256
#define MAXN  50176
#define MAXE  802816
#define SCAN_CHUNK 4096
#define MAXB  16            // max scan blocks: ceil(50000/4096)=13

// -------- scratch (static device globals: no runtime allocation) --------
__device__ int   g_deg[MAXN];      // statically zero; every call leaves it zero
__device__ int   g_off[MAXN + 1];
__device__ int   g_cur[MAXN];
__device__ int   g_bsum[MAXB];
__device__ __align__(16) int2   g_edge[MAXE];                 // bucketed (src, w_bits)
__device__ __align__(16) __half g_hw16[(size_t)MAXN * DIM];   // fp16 hW = h @ W

// ======== TF32 GEMM tile body (device function; called from fused kernels) ========
// 128x64 tile, BK=32, 256 threads (8 warps), warp = 32x32 (2x4 m16n8 tiles).
#define GBM 128
#define GBN 64
#define GBK 32
#define A_PITCH 36
#define B_PITCH 72

__device__ __forceinline__ float to_tf32(float x) {
    float y;
    asm("cvt.rna.tf32.f32 %0, %1;" : "=f"(y) : "f"(x));
    return y;
}

__device__ __forceinline__ void mma_tf32(float& d0, float& d1, float& d2, float& d3,
                                         uint32_t a0, uint32_t a1, uint32_t a2, uint32_t a3,
                                         uint32_t b0, uint32_t b1) {
    asm volatile(
        "mma.sync.aligned.m16n8k8.row.col.f32.tf32.tf32.f32 "
        "{%0,%1,%2,%3}, {%4,%5,%6,%7}, {%8,%9}, {%0,%1,%2,%3};"
        : "+f"(d0), "+f"(d1), "+f"(d2), "+f"(d3)
        : "r"(a0), "r"(a1), "r"(a2), "r"(a3), "r"(b0), "r"(b1));
}

__device__ void gemm_tile_body(const float* __restrict__ A,   // h [M,256]
                               const float* __restrict__ W,   // [256,256]
                               int M, int tile_m, int tile_n) {
    __shared__ float As[GBM * A_PITCH];
    __shared__ float Bs[GBK * B_PITCH];

    const int tid    = threadIdx.x;
    const int warp   = tid >> 5;
    const int lane   = tid & 31;
    const int gid    = lane >> 2;
    const int tig    = lane & 3;
    const int warp_m = warp >> 1;
    const int warp_n = warp & 1;
    const int wm0    = warp_m * 32;
    const int wn0    = warp_n * 32;

    float acc[2][4][4];
    #pragma unroll
    for (int i = 0; i < 2; i++)
        #pragma unroll
        for (int j = 0; j < 4; j++)
            #pragma unroll
            for (int r = 0; r < 4; r++) acc[i][j][r] = 0.0f;

    const int a_row = tid >> 3;
    const int a_q   = tid & 7;
    const int b_row = tid >> 4;
    const int b_q   = tid & 15;

    float4 ra[4], rb[2];

    #pragma unroll
    for (int it = 0; it < 4; it++) {
        int gm = tile_m + a_row + it * 32;
        ra[it] = (gm < M) ? *reinterpret_cast<const float4*>(&A[(size_t)gm * DIM + a_q * 4])
                          : make_float4(0.f, 0.f, 0.f, 0.f);
    }
    #pragma unroll
    for (int it = 0; it < 2; it++)
        rb[it] = *reinterpret_cast<const float4*>(
            &W[(size_t)(b_row + it * 16) * DIM + tile_n + b_q * 4]);

    const int NK = DIM / GBK;   // 8
    for (int kt = 0; kt < NK; kt++) {
        #pragma unroll
        for (int it = 0; it < 4; it++) {
            float4 v = ra[it];
            v.x = to_tf32(v.x); v.y = to_tf32(v.y);
            v.z = to_tf32(v.z); v.w = to_tf32(v.w);
            *reinterpret_cast<float4*>(&As[(a_row + it * 32) * A_PITCH + a_q * 4]) = v;
        }
        #pragma unroll
        for (int it = 0; it < 2; it++) {
            float4 v = rb[it];
            v.x = to_tf32(v.x); v.y = to_tf32(v.y);
            v.z = to_tf32(v.z); v.w = to_tf32(v.w);
            *reinterpret_cast<float4*>(&Bs[(b_row + it * 16) * B_PITCH + b_q * 4]) = v;
        }
        __syncthreads();

        if (kt + 1 < NK) {
            const int k0 = (kt + 1) * GBK;
            #pragma unroll
            for (int it = 0; it < 4; it++) {
                int gm = tile_m + a_row + it * 32;
                ra[it] = (gm < M) ? *reinterpret_cast<const float4*>(
                                        &A[(size_t)gm * DIM + k0 + a_q * 4])
                                  : make_float4(0.f, 0.f, 0.f, 0.f);
            }
            #pragma unroll
            for (int it = 0; it < 2; it++)
                rb[it] = *reinterpret_cast<const float4*>(
                    &W[(size_t)(k0 + b_row + it * 16) * DIM + tile_n + b_q * 4]);
        }

        #pragma unroll
        for (int kk = 0; kk < GBK / 8; kk++) {
            const int kb = kk * 8;
            uint32_t a[2][4], b[4][2];
            #pragma unroll
            for (int mt = 0; mt < 2; mt++) {
                int m0 = wm0 + mt * 16;
                a[mt][0] = __float_as_uint(As[(m0 + gid)     * A_PITCH + kb + tig]);
                a[mt][1] = __float_as_uint(As[(m0 + 8 + gid) * A_PITCH + kb + tig]);
                a[mt][2] = __float_as_uint(As[(m0 + gid)     * A_PITCH + kb + tig + 4]);
                a[mt][3] = __float_as_uint(As[(m0 + 8 + gid) * A_PITCH + kb + tig + 4]);
            }
            #pragma unroll
            for (int nt = 0; nt < 4; nt++) {
                int n0 = wn0 + nt * 8 + gid;
                b[nt][0] = __float_as_uint(Bs[(kb + tig)     * B_PITCH + n0]);
                b[nt][1] = __float_as_uint(Bs[(kb + tig + 4) * B_PITCH + n0]);
            }
            #pragma unroll
            for (int mt = 0; mt < 2; mt++)
                #pragma unroll
                for (int nt = 0; nt < 4; nt++)
                    mma_tf32(acc[mt][nt][0], acc[mt][nt][1], acc[mt][nt][2], acc[mt][nt][3],
                             a[mt][0], a[mt][1], a[mt][2], a[mt][3],
                             b[nt][0], b[nt][1]);
        }
        __syncthreads();
    }

    // epilogue: store fp16 (bias is added post-aggregation)
    #pragma unroll
    for (int mt = 0; mt < 2; mt++) {
        int r0 = tile_m + wm0 + mt * 16 + gid;
        int r1 = r0 + 8;
        #pragma unroll
        for (int nt = 0; nt < 4; nt++) {
            int gc = tile_n + wn0 + nt * 8 + tig * 2;
            if (r0 < M) {
                __half2 o = __floats2half2_rn(acc[mt][nt][0], acc[mt][nt][1]);
                *reinterpret_cast<__half2*>(&g_hw16[(size_t)r0 * DIM + gc]) = o;
            }
            if (r1 < M) {
                __half2 o = __floats2half2_rn(acc[mt][nt][2], acc[mt][nt][3]);
                *reinterpret_cast<__half2*>(&g_hw16[(size_t)r1 * DIM + gc]) = o;
            }
        }
    }
}

// -------- fused 1: hist blocks [0, nHist) + GEMM tiles [tile0, tile0+...) --------
__global__ __launch_bounds__(256)
void k_fused1(const int4* __restrict__ dst4, int E4,
              const float* __restrict__ h, const float* __restrict__ W, int M,
              int nHist, int tile0) {
    if ((int)blockIdx.x < nHist) {
        int e = blockIdx.x * blockDim.x + threadIdx.x;
        if (e < E4) {
            int4 d = dst4[e];
            atomicAdd(&g_deg[d.x], 1);
            atomicAdd(&g_deg[d.y], 1);
            atomicAdd(&g_deg[d.z], 1);
            atomicAdd(&g_deg[d.w], 1);
        }
    } else {
        int t = tile0 + ((int)blockIdx.x - nHist);
        gemm_tile_body(h, W, M, (t >> 2) * GBM, (t & 3) * GBN);
    }
}

// -------- fused 2: bucket blocks [0, nBucket) + GEMM tiles [tile0, ...) --------
__global__ __launch_bounds__(256)
void k_fused2(const int4* __restrict__ src4, const int4* __restrict__ dst4,
              const float4* __restrict__ ew4, int E4,
              const float* __restrict__ h, const float* __restrict__ W, int M,
              int nBucket, int tile0) {
    if ((int)blockIdx.x < nBucket) {
        int e = blockIdx.x * blockDim.x + threadIdx.x;
        if (e < E4) {
            int4   s = src4[e];
            int4   d = dst4[e];
            float4 w = ew4[e];
            int p0 = atomicAdd(&g_cur[d.x], 1);
            int p1 = atomicAdd(&g_cur[d.y], 1);
            int p2 = atomicAdd(&g_cur[d.z], 1);
            int p3 = atomicAdd(&g_cur[d.w], 1);
            g_edge[p0] = make_int2(s.x, __float_as_int(w.x));
            g_edge[p1] = make_int2(s.y, __float_as_int(w.y));
            g_edge[p2] = make_int2(s.z, __float_as_int(w.z));
            g_edge[p3] = make_int2(s.w, __float_as_int(w.w));
        }
    } else {
        int t = tile0 + ((int)blockIdx.x - nBucket);
        gemm_tile_body(h, W, M, (t >> 2) * GBM, (t & 3) * GBN);
    }
}

// -------- tails (only launched when E % 4 != 0; not the case for E=800000) --------
__global__ void k_hist_tail(const int* __restrict__ dst, int start, int E) {
    int e = start + blockIdx.x * blockDim.x + threadIdx.x;
    if (e < E) atomicAdd(&g_deg[dst[e]], 1);
}
__global__ void k_bucket_tail(const int* __restrict__ src,
                              const int* __restrict__ dst,
                              const float* __restrict__ e_w, int start, int E) {
    int e = start + blockIdx.x * blockDim.x + threadIdx.x;
    if (e < E) {
        int pos = atomicAdd(&g_cur[dst[e]], 1);
        g_edge[pos] = make_int2(src[e], __float_as_int(e_w[e]));
    }
}

// -------- 2a. per-block scan (4096 elems/block); ALSO resets g_deg to zero --------
__global__ __launch_bounds__(1024)
void k_scan_blk(int N) {
    __shared__ int warp_sums[32];
    const int tid  = threadIdx.x;
    const int lane = tid & 31;
    const int warp = tid >> 5;
    const int i0   = blockIdx.x * SCAN_CHUNK + tid * 4;

    int v[4];
    #pragma unroll
    for (int j = 0; j < 4; j++) {
        int i = i0 + j;
        v[j] = (i < N) ? g_deg[i] : 0;
        if (i < N) g_deg[i] = 0;          // leave counters zeroed for the next call
    }
    int tsum = v[0] + v[1] + v[2] + v[3];

    int x = tsum;
    #pragma unroll
    for (int d = 1; d < 32; d <<= 1) {
        int y = __shfl_up_sync(0xffffffffu, x, d);
        if (lane >= d) x += y;
    }
    if (lane == 31) warp_sums[warp] = x;
    __syncthreads();
    if (warp == 0) {
        int ws = warp_sums[lane];
        #pragma unroll
        for (int d = 1; d < 32; d <<= 1) {
            int y = __shfl_up_sync(0xffffffffu, ws, d);
            if (lane >= d) ws += y;
        }
        warp_sums[lane] = ws;
    }
    __syncthreads();

    int warp_off = (warp == 0) ? 0 : warp_sums[warp - 1];
    int excl = warp_off + (x - tsum);
    #pragma unroll
    for (int j = 0; j < 4; j++) {
        int i = i0 + j;
        if (i < N) g_off[i] = excl;
        excl += v[j];
    }
    if (tid == 0) g_bsum[blockIdx.x] = warp_sums[31];
}

// -------- 2b. add block offsets (top-level 13-elem scan done redundantly per block) --------
__global__ __launch_bounds__(1024)
void k_scan_add(int nb, int N) {
    __shared__ int s_boff[MAXB];
    __shared__ int s_total;

    if (threadIdx.x < 32) {
        const int lane = threadIdx.x;
        int b = (lane < nb) ? g_bsum[lane] : 0;
        int x = b;
        #pragma unroll
        for (int d = 1; d < 32; d <<= 1) {
            int y = __shfl_up_sync(0xffffffffu, x, d);
            if (lane >= d) x += y;
        }
        if (lane < nb) s_boff[lane] = x - b;     // exclusive
        if (lane == 31) s_total = x;
    }
    __syncthreads();

    int i = blockIdx.x * blockDim.x + threadIdx.x;
    if (i < N) {
        int off = g_off[i] + s_boff[i / SCAN_CHUNK];
        g_off[i] = off;
        g_cur[i] = off;
    }
    if (blockIdx.x == 0 && threadIdx.x == 0) g_off[N] = s_total;
}

// -------- aggregation over hW16: 8 nodes/block, 32 threads/node, uint4 lanes --------
__device__ __forceinline__ void acc_edge(const uint4& u, float ew,
                                         float4& acc0, float4& acc1) {
    float2 p0 = __half22float2(*reinterpret_cast<const __half2*>(&u.x));
    float2 p1 = __half22float2(*reinterpret_cast<const __half2*>(&u.y));
    float2 p2 = __half22float2(*reinterpret_cast<const __half2*>(&u.z));
    float2 p3 = __half22float2(*reinterpret_cast<const __half2*>(&u.w));
    acc0.x = fmaf(p0.x, ew, acc0.x); acc0.y = fmaf(p0.y, ew, acc0.y);
    acc0.z = fmaf(p1.x, ew, acc0.z); acc0.w = fmaf(p1.y, ew, acc0.w);
    acc1.x = fmaf(p2.x, ew, acc1.x); acc1.y = fmaf(p2.y, ew, acc1.y);
    acc1.z = fmaf(p3.x, ew, acc1.z); acc1.w = fmaf(p3.y, ew, acc1.w);
}

__global__ __launch_bounds__(256)
void k_agg(const float* __restrict__ bias, float* __restrict__ out, int N) {
    const int t    = threadIdx.x;
    const int grp  = t >> 5;            // 0..7: node within block
    const int lane = t & 31;            // uint4 (8-feature) index within row
    const int n = blockIdx.x * 8 + grp;
    if (n >= N) return;

    const uint4* __restrict__ hw = reinterpret_cast<const uint4*>(g_hw16);  // row = 32 uint4

    int i         = g_off[n];
    const int end = g_off[n + 1];

    float4 acc0 = make_float4(0.f, 0.f, 0.f, 0.f);
    float4 acc1 = make_float4(0.f, 0.f, 0.f, 0.f);

    for (; i + 4 <= end; i += 4) {
        int2 e0 = g_edge[i], e1 = g_edge[i+1], e2 = g_edge[i+2], e3 = g_edge[i+3];
        float w0 = __int_as_float(e0.y), w1 = __int_as_float(e1.y);
        float w2 = __int_as_float(e2.y), w3 = __int_as_float(e3.y);
        uint4 u0 = __ldg(&hw[(size_t)e0.x * 32 + lane]);
        uint4 u1 = __ldg(&hw[(size_t)e1.x * 32 + lane]);
        uint4 u2 = __ldg(&hw[(size_t)e2.x * 32 + lane]);
        uint4 u3 = __ldg(&hw[(size_t)e3.x * 32 + lane]);
        acc_edge(u0, w0, acc0, acc1);
        acc_edge(u1, w1, acc0, acc1);
        acc_edge(u2, w2, acc0, acc1);
        acc_edge(u3, w3, acc0, acc1);
    }
    for (; i < end; i++) {
        int2 e = g_edge[i];
        float ew = __int_as_float(e.y);
        uint4 u = __ldg(&hw[(size_t)e.x * 32 + lane]);
        acc_edge(u, ew, acc0, acc1);
    }

    float4 bv0 = *reinterpret_cast<const float4*>(&bias[lane * 8]);
    float4 bv1 = *reinterpret_cast<const float4*>(&bias[lane * 8 + 4]);
    acc0.x += bv0.x; acc0.y += bv0.y; acc0.z += bv0.z; acc0.w += bv0.w;
    acc1.x += bv1.x; acc1.y += bv1.y; acc1.z += bv1.z; acc1.w += bv1.w;

    float4* orow = reinterpret_cast<float4*>(out) + (size_t)n * 64 + lane * 2;
    orow[0] = acc0;
    orow[1] = acc1;
}

extern "C" void kernel_launch(void* const* d_in, const int* in_sizes, int n_in,
                              void* d_out, int out_size) {
    const float* h      = (const float*)d_in[0];   // [N, 256]
    const float* e_w    = (const float*)d_in[1];   // [E, 1]
    const int*   src    = (const int*)  d_in[2];   // [E]
    const int*   dst    = (const int*)  d_in[3];   // [E]
    const float* weight = (const float*)d_in[4];   // [256, 256]
    const float* bias   = (const float*)d_in[5];   // [256]
    float* out = (float*)d_out;                    // [N, 256]

    const int N = in_sizes[0] / DIM;
    const int E = in_sizes[2];

    const int E4      = E / 4;
    const int nHist   = (E4 + 255) / 256;                  // 782
    const int nBucket = nHist;
    const int mTiles  = (N + GBM - 1) / GBM;               // 391
    const int nTiles  = DIM / GBN;                         // 4
    const int totalTiles = mTiles * nTiles;                // 1564
    const int tilesA  = totalTiles / 2;                    // 782 (with fused1)
    const int tilesB  = totalTiles - tilesA;               // 782 (with fused2)

    // fused1: hist + first half of GEMM (independent chains co-scheduled)
    k_fused1<<<nHist + tilesA, 256>>>((const int4*)dst, E4, h, weight, N, nHist, 0);
    if (E4 * 4 < E)
        k_hist_tail<<<1, 256>>>(dst, E4 * 4, E);

    const int nb = (N + SCAN_CHUNK - 1) / SCAN_CHUNK;      // 13
    k_scan_blk<<<nb, 1024>>>(N);                           // also re-zeros g_deg
    k_scan_add<<<(N + 1023) / 1024, 1024>>>(nb, N);        // top-scan fused in

    // fused2: bucket + second half of GEMM
    k_fused2<<<nBucket + tilesB, 256>>>((const int4*)src, (const int4*)dst,
                                        (const float4*)e_w, E4, h, weight, N,
                                        nBucket, tilesA);
    if (E4 * 4 < E)
        k_bucket_tail<<<1, 256>>>(src, dst, e_w, E4 * 4, E);

    // aggregate over hW16 (needs full g_edge + full g_hw16), fuse bias, write out
    k_agg<<<(N + 7) / 8, 256>>>(bias, out, N);
}